// round 14
// baseline (speedup 1.0000x reference)
#include <cuda_runtime.h>

#define CHUNK  256
#define MAXW   40
#define MAXN   (MAXW * CHUNK)   // 10240
#define MAXP   1000
#define SB     4096
#define KCAP   1280              // stop fires by 1000 => K <= 999+256 < 1280

typedef unsigned long long u64;

// ---- static device scratch (no allocations allowed) ----
__device__ ulonglong4 g_maskT[(size_t)MAXW * MAXN];  // [word][row] 256-bit rows
__device__ ulonglong4 g_diag[MAXN];                  // diagonal-tile masks
__device__ float4     g_sboxes[MAXN];                // boxes in sorted order
__device__ float      g_sscores[MAXN];               // scores in sorted order
__device__ u64        g_keep[MAXW * 4];              // keep bits, 4 u64/chunk
__device__ int        g_prefixw[MAXW * 4];           // rank base per 64-bit word
__device__ int        g_base[SB];                    // bucket base (descending)
__device__ int        g_members[MAXN];               // indices grouped by bucket

__device__ __forceinline__ int bucket_of(float s) {
    int b = (int)(s * 4096.0f);           // monotone for s >= 0
    return max(0, min(SB - 1, b));
}

// ---------------------------------------------------------------------------
// S1: fused single-block sort front-end: histogram + descending exclusive
// scan + bucket fill. All bucket state in shared (no cross-replay cleanup).
// ---------------------------------------------------------------------------
__global__ void k_sortA(const float* __restrict__ scores, int N) {
    __shared__ int s_cnt[SB];
    __shared__ int s_base[SB];
    __shared__ int wsum[32];
    int tid = threadIdx.x, lane = tid & 31, wid = tid >> 5;

    for (int b = tid; b < SB; b += 1024) s_cnt[b] = 0;
    __syncthreads();
    for (int i = tid; i < N; i += 1024)
        atomicAdd(&s_cnt[bucket_of(scores[i])], 1);
    __syncthreads();

    int cbase = 0;
    for (int k = 0; k < SB / 1024; k++) {
        int b = SB - 1 - (k * 1024 + tid);   // descending bucket order
        int v = s_cnt[b];
        int x = v;
        #pragma unroll
        for (int o = 1; o < 32; o <<= 1) {
            int y = __shfl_up_sync(~0u, x, o);
            if (lane >= o) x += y;
        }
        if (lane == 31) wsum[wid] = x;
        __syncthreads();
        if (wid == 0) {
            int s = wsum[lane];
            #pragma unroll
            for (int o = 1; o < 32; o <<= 1) {
                int y = __shfl_up_sync(~0u, s, o);
                if (lane >= o) s += y;
            }
            wsum[lane] = s;
        }
        __syncthreads();
        s_base[b] = cbase + (x - v) + (wid ? wsum[wid - 1] : 0);
        cbase += wsum[31];
        __syncthreads();
    }

    for (int b = tid; b < SB; b += 1024) { s_cnt[b] = 0; g_base[b] = s_base[b]; }
    __syncthreads();
    for (int i = tid; i < N; i += 1024) {
        int b = bucket_of(scores[i]);
        int slot = s_base[b] + atomicAdd(&s_cnt[b], 1);
        g_members[slot] = i;
    }
}

// ---------------------------------------------------------------------------
// S2: exact stable rank within bucket + scatter (grid-parallel).
// ---------------------------------------------------------------------------
__global__ void k_place(const float4* __restrict__ boxes,
                        const float* __restrict__ scores, int N) {
    int i = blockIdx.x * blockDim.x + threadIdx.x;
    if (i >= N) return;
    float si = scores[i];
    int b = bucket_of(si);
    int base = g_base[b];
    int cb   = ((b > 0) ? g_base[b - 1] : N) - base;
    int r = base;
    for (int t = 0; t < cb; t++) {
        int j = g_members[base + t];
        if (j == i) continue;
        float sj = scores[j];
        r += (sj > si) || (sj == si && j < i);
    }
    g_sboxes[r]  = boxes[i];
    g_sscores[r] = si;
}

// ---------------------------------------------------------------------------
// K2: pairwise IoU suppression bitmask, 256x256 tiles, upper triangle.
// suppress <=> IoU > 0.5 <=> 3*inter > areaR + areaC  (division-free).
// Padding boxes all-zero -> never suppress.
// ---------------------------------------------------------------------------
__global__ void k_mask(int N, int W) {
    int cb = blockIdx.x, rb = blockIdx.y;
    if (cb < rb) return;
    __shared__ float4 cbox[CHUNK];
    __shared__ float  carea[CHUNK];
    int t  = threadIdx.x;
    int cg = cb * CHUNK + t;
    float4 cv = (cg < N) ? g_sboxes[cg] : make_float4(0.f, 0.f, 0.f, 0.f);
    cbox[t]  = cv;
    carea[t] = (cv.z - cv.x) * (cv.w - cv.y);
    __syncthreads();

    int rg = rb * CHUNK + t;
    if (rg >= N) return;
    float4 r = g_sboxes[rg];
    float ra = (r.z - r.x) * (r.w - r.y);

    u64 m[4] = {0ull, 0ull, 0ull, 0ull};
    if (cb > rb) {
        #pragma unroll
        for (int q = 0; q < 4; q++) {
            u64 mm = 0ull;
            #pragma unroll 32
            for (int jj = 0; jj < 64; jj++) {
                int j = q * 64 + jj;
                float4 c = cbox[j];
                float ix1 = fmaxf(r.x, c.x), iy1 = fmaxf(r.y, c.y);
                float ix2 = fminf(r.z, c.z), iy2 = fminf(r.w, c.w);
                float inter = fmaxf(ix2 - ix1, 0.0f) * fmaxf(iy2 - iy1, 0.0f);
                if (3.0f * inter > ra + carea[j]) mm |= 1ull << jj;
            }
            m[q] = mm;
        }
    } else {
        // diagonal tile: only suppress later (lower-score) boxes j > t
        #pragma unroll 4
        for (int j = 0; j < CHUNK; j++) {
            if (j <= t) continue;
            float4 c = cbox[j];
            float ix1 = fmaxf(r.x, c.x), iy1 = fmaxf(r.y, c.y);
            float ix2 = fminf(r.z, c.z), iy2 = fminf(r.w, c.w);
            float inter = fmaxf(ix2 - ix1, 0.0f) * fmaxf(iy2 - iy1, 0.0f);
            if (3.0f * inter > ra + carea[j]) m[j >> 6] |= 1ull << (j & 63);
        }
        g_diag[rg] = make_ulonglong4(m[0], m[1], m[2], m[3]);
    }
    g_maskT[(size_t)cb * MAXN + rg] = make_ulonglong4(m[0], m[1], m[2], m[3]);
}

__device__ __forceinline__ u64 vmask64(int valid) {
    return (valid >= 64) ? ~0ull : ((valid <= 0) ? 0ull : ((1ull << valid) - 1ull));
}

// ---------------------------------------------------------------------------
// phase A, optimistic batch version over a 256-wide chunk (4 u64 words).
// Tentatively keep ALL pending bits; batch-OR their diag rows (independent
// LDS); if (OR & pending)==0 the chunk resolves in one pass. Otherwise bits
// below the first conflicted bit f are provably kept, f provably suppressed;
// re-batch the remainder (rare). Appends kept global ids to klist.
// ---------------------------------------------------------------------------
__device__ __forceinline__ int phaseA_opt4(const ulonglong4* d,
                                           const u64 r[4], int valid,
                                           int gbase, int* klist, u64 kout[4]) {
    u64 P[4], c[4], sup[4];
    #pragma unroll
    for (int q = 0; q < 4; q++) {
        P[q] = ~r[q] & vmask64(valid - q * 64);
        c[q] = 0ull; sup[q] = 0ull;
    }
    int n = 0;
    while (P[0] | P[1] | P[2] | P[3]) {
        int nck = n;                   // klist checkpoint
        u64 o[4] = {0ull, 0ull, 0ull, 0ull};
        #pragma unroll
        for (int q = 0; q < 4; q++) {
            u64 t = P[q];
            while (t) {
                int i = __ffsll((long long)t) - 1; t &= t - 1ull;
                klist[n++] = gbase + q * 64 + i;
                ulonglong4 dd = d[q * 64 + i];
                o[0] |= dd.x; o[1] |= dd.y; o[2] |= dd.z; o[3] |= dd.w;
            }
        }
        u64 x[4];
        #pragma unroll
        for (int q = 0; q < 4; q++) x[q] = (sup[q] | o[q]) & P[q];
        if (!(x[0] | x[1] | x[2] | x[3])) {        // happy path
            #pragma unroll
            for (int q = 0; q < 4; q++) c[q] |= P[q];
            break;
        }

        // conflict: locate first conflicted bit f
        n = nck;                       // rewind klist
        int fw = 0;
        if (x[0]) fw = 0; else if (x[1]) fw = 1; else if (x[2]) fw = 2; else fw = 3;
        int fb = __ffsll((long long)x[fw]) - 1;
        u64 m[4];
        #pragma unroll
        for (int q = 0; q < 4; q++)
            m[q] = (q < fw) ? ~0ull : ((q == fw) ? ((1ull << fb) - 1ull) : 0ull);

        #pragma unroll
        for (int q = 0; q < 4; q++) {
            u64 nc = P[q] & m[q];                 // newly confirmed kept
            c[q] |= nc;
            u64 t = nc;
            while (t) {
                int i = __ffsll((long long)t) - 1; t &= t - 1ull;
                klist[n++] = gbase + q * 64 + i;
                ulonglong4 dd = d[q * 64 + i];
                sup[0] |= dd.x; sup[1] |= dd.y; sup[2] |= dd.z; sup[3] |= dd.w;
            }
        }
        #pragma unroll
        for (int q = 0; q < 4; q++) P[q] = P[q] & ~m[q] & ~sup[q];
        P[fw] &= ~(1ull << fb);                   // f itself is suppressed
    }
    #pragma unroll
    for (int q = 0; q < 4; q++) kout[q] = c[q];
    return n;
}

// ---------------------------------------------------------------------------
// K3: lazy greedy scan over 256-wide chunks (39 rounds).
//   phase 1: ALL 256 threads gather OR over the global kept list of
//            maskT[wc][kept_row]  (independent 32B loads, 8 warps).
//   phase 2: thread 0 reduces partials + optimistic phase A; threads
//            128..255 prefetch diag tile wc+1 (double-buffered).
// Early termination once total kept >= MAXP.
// ---------------------------------------------------------------------------
__global__ void k_scan(int N, int W) {
    __shared__ ulonglong4 diagbuf[2][CHUNK];   // 16 KB
    __shared__ ulonglong4 s_part[8];
    __shared__ int s_klist[KCAP];
    __shared__ int s_K, s_stop, s_cstop, s_total;
    int tid = threadIdx.x, lane = tid & 31, wid = tid >> 5;
    ulonglong4 Z4 = make_ulonglong4(0ull, 0ull, 0ull, 0ull);

    diagbuf[0][tid] = (tid < N) ? g_diag[tid] : Z4;
    {
        int g = CHUNK + tid;
        diagbuf[1][tid] = (W > 1 && g < N) ? g_diag[g] : Z4;
    }
    if (tid == 0) { s_stop = 0; s_cstop = W; s_total = 0; s_K = 0; }
    __syncthreads();

    // chunk 0
    if (tid == 0) {
        u64 r0[4] = {0ull, 0ull, 0ull, 0ull};
        u64 kw[4];
        int n = phaseA_opt4(diagbuf[0], r0, min(N, CHUNK), 0, s_klist, kw);
        int base = 0;
        #pragma unroll
        for (int q = 0; q < 4; q++) {
            g_keep[q] = kw[q];
            g_prefixw[q] = base;
            base += __popcll(kw[q]);
        }
        s_total = base; s_K = n;
        if (base >= MAXP) { s_stop = 1; s_cstop = 1; }
    }
    __syncthreads();

    for (int wc = 1; wc < W; wc++) {
        if (s_stop) break;
        int pb = wc & 1;
        int K = s_K;

        // phase 1: cooperative gather of chunk wc's 256-bit suppression word
        const ulonglong4* mp = g_maskT + (size_t)wc * MAXN;
        u64 a0 = 0, a1 = 0, a2 = 0, a3 = 0;
        for (int t = tid; t < K; t += 256) {
            ulonglong4 v = mp[s_klist[t]];
            a0 |= v.x; a1 |= v.y; a2 |= v.z; a3 |= v.w;
        }
        #pragma unroll
        for (int o = 16; o; o >>= 1) {
            a0 |= __shfl_xor_sync(~0u, a0, o);
            a1 |= __shfl_xor_sync(~0u, a1, o);
            a2 |= __shfl_xor_sync(~0u, a2, o);
            a3 |= __shfl_xor_sync(~0u, a3, o);
        }
        if (lane == 0) s_part[wid] = make_ulonglong4(a0, a1, a2, a3);
        __syncthreads();

        // phase 2: thread 0 reduce + phase A; tid>=128 prefetch diag wc+1
        if (tid == 0) {
            u64 r[4] = {0ull, 0ull, 0ull, 0ull};
            #pragma unroll
            for (int p = 0; p < 8; p++) {
                ulonglong4 v = s_part[p];
                r[0] |= v.x; r[1] |= v.y; r[2] |= v.z; r[3] |= v.w;
            }
            u64 kw[4];
            int n = phaseA_opt4(diagbuf[pb], r, N - wc * CHUNK,
                                wc * CHUNK, s_klist + K, kw);
            int base = s_total;
            #pragma unroll
            for (int q = 0; q < 4; q++) {
                g_keep[wc * 4 + q] = kw[q];
                g_prefixw[wc * 4 + q] = base;
                base += __popcll(kw[q]);
            }
            s_total = base; s_K = K + n;
            if (base >= MAXP) { s_stop = 1; s_cstop = wc + 1; }
        } else if (tid >= 128 && wc + 1 < W) {
            int t = tid - 128;          // 0..127, two rows each
            int g0 = (wc + 1) * CHUNK + t;
            int g1 = g0 + 128;
            diagbuf[pb ^ 1][t]       = (g0 < N) ? g_diag[g0] : Z4;
            diagbuf[pb ^ 1][t + 128] = (g1 < N) ? g_diag[g1] : Z4;
        }
        __syncthreads();
    }

    // chunks after the stop point can never contribute kept outputs
    int cstop = s_cstop;
    for (int idx = cstop * 4 + tid; idx < W * 4; idx += 256) g_keep[idx] = 0ull;
}

// ---------------------------------------------------------------------------
// K4: apply MAX_PROPOSALS cutoff and emit outputs:
//   out[0 : 4N) boxes | out[4N : 5N) scores | out[5N : 6N) keep as 0/1
// ---------------------------------------------------------------------------
__global__ void k_out(float* __restrict__ out, int N) {
    int p = blockIdx.x * blockDim.x + threadIdx.x;
    if (p >= N) return;
    int widx = p >> 6;        // global 64-bit word index == (chunk*4 + word)
    int ii   = p & 63;
    u64 kw = g_keep[widx];
    bool kept = (kw >> ii) & 1ull;
    int r = g_prefixw[widx] + __popcll(kw & ((1ull << ii) - 1ull));
    bool fin = kept && (r < MAXP);

    float4 b = fin ? g_sboxes[p] : make_float4(0.f, 0.f, 0.f, 0.f);
    ((float4*)out)[p] = b;
    out[4 * N + p] = fin ? g_sscores[p] : 0.0f;
    out[5 * N + p] = fin ? 1.0f : 0.0f;
}

// ---------------------------------------------------------------------------
extern "C" void kernel_launch(void* const* d_in, const int* in_sizes, int n_in,
                              void* d_out, int out_size) {
    const float4* boxes  = (const float4*)d_in[0];
    const float*  scores = (const float*)d_in[1];
    int N = in_sizes[1];
    int W = (N + CHUNK - 1) / CHUNK;

    k_sortA<<<1, 1024>>>(scores, N);
    k_place<<<(N + 255) / 256, 256>>>(boxes, scores, N);

    dim3 g2(W, W);
    k_mask<<<g2, CHUNK>>>(N, W);

    k_scan<<<1, 256>>>(N, W);

    k_out<<<(N + 255) / 256, 256>>>((float*)d_out, N);
}

// round 15
// speedup vs baseline: 1.2303x; 1.2303x over previous
#include <cuda_runtime.h>

#define CHUNK  128
#define MAXW   79
#define MAXN   (MAXW * CHUNK)   // 10112
#define MAXP   1000
#define SB     4096
#define KCAP   1280              // stop by 1000 => K <= 999+128+128 < 1280

typedef unsigned long long u64;

// ---- static device scratch (no allocations allowed) ----
__device__ ulonglong2 g_maskT[(size_t)MAXW * MAXN];  // [word][row] suppression bits
__device__ ulonglong2 g_diag[MAXN];                  // diagonal-block masks
__device__ float4     g_sboxes[MAXN];                // boxes in sorted order
__device__ float      g_sscores[MAXN];               // scores in sorted order
__device__ ulonglong2 g_keep[MAXW];                  // keep bits per 128-chunk
__device__ int        g_prefix[MAXW];                // kept-count prefix per chunk
__device__ int        g_base[SB];                    // bucket base (descending order)
__device__ int        g_members[MAXN];               // indices grouped by bucket

__device__ __forceinline__ int bucket_of(float s) {
    int b = (int)(s * 4096.0f);           // monotone for s >= 0
    return max(0, min(SB - 1, b));
}

// ---------------------------------------------------------------------------
// S1: fused single-block sort front-end: histogram + descending exclusive
// scan + bucket fill. All bucket state in shared (no cross-replay cleanup).
// ---------------------------------------------------------------------------
__global__ void k_sortA(const float* __restrict__ scores, int N) {
    __shared__ int s_cnt[SB];
    __shared__ int s_base[SB];
    __shared__ int wsum[32];
    int tid = threadIdx.x, lane = tid & 31, wid = tid >> 5;

    for (int b = tid; b < SB; b += 1024) s_cnt[b] = 0;
    __syncthreads();
    for (int i = tid; i < N; i += 1024)
        atomicAdd(&s_cnt[bucket_of(scores[i])], 1);
    __syncthreads();

    int cbase = 0;
    for (int k = 0; k < SB / 1024; k++) {
        int b = SB - 1 - (k * 1024 + tid);   // descending bucket order
        int v = s_cnt[b];
        int x = v;
        #pragma unroll
        for (int o = 1; o < 32; o <<= 1) {
            int y = __shfl_up_sync(~0u, x, o);
            if (lane >= o) x += y;
        }
        if (lane == 31) wsum[wid] = x;
        __syncthreads();
        if (wid == 0) {
            int s = wsum[lane];
            #pragma unroll
            for (int o = 1; o < 32; o <<= 1) {
                int y = __shfl_up_sync(~0u, s, o);
                if (lane >= o) s += y;
            }
            wsum[lane] = s;
        }
        __syncthreads();
        s_base[b] = cbase + (x - v) + (wid ? wsum[wid - 1] : 0);
        cbase += wsum[31];
        __syncthreads();
    }

    for (int b = tid; b < SB; b += 1024) { s_cnt[b] = 0; g_base[b] = s_base[b]; }
    __syncthreads();
    for (int i = tid; i < N; i += 1024) {
        int b = bucket_of(scores[i]);
        int slot = s_base[b] + atomicAdd(&s_cnt[b], 1);
        g_members[slot] = i;
    }
}

// ---------------------------------------------------------------------------
// S2: exact stable rank within bucket + scatter (grid-parallel).
// ---------------------------------------------------------------------------
__global__ void k_place(const float4* __restrict__ boxes,
                        const float* __restrict__ scores, int N) {
    int i = blockIdx.x * blockDim.x + threadIdx.x;
    if (i >= N) return;
    float si = scores[i];
    int b = bucket_of(si);
    int base = g_base[b];
    int cb   = ((b > 0) ? g_base[b - 1] : N) - base;
    int r = base;
    for (int t = 0; t < cb; t++) {
        int j = g_members[base + t];
        if (j == i) continue;
        float sj = scores[j];
        r += (sj > si) || (sj == si && j < i);
    }
    g_sboxes[r]  = boxes[i];
    g_sscores[r] = si;
}

// ---------------------------------------------------------------------------
// K2: pairwise IoU suppression bitmask, 128x128 tiles, upper triangle.
// suppress <=> IoU > 0.5 <=> 3*inter > areaR + areaC  (division-free).
// Stores TRANSPOSED: g_maskT[word][row].
// ---------------------------------------------------------------------------
__global__ void k_mask(int N, int W) {
    int cb = blockIdx.x, rb = blockIdx.y;
    if (cb < rb) return;
    __shared__ float4 cbox[CHUNK];
    __shared__ float  carea[CHUNK];
    int t  = threadIdx.x;
    int cg = cb * CHUNK + t;
    float4 cv = (cg < N) ? g_sboxes[cg] : make_float4(0.f, 0.f, 0.f, 0.f);
    cbox[t]  = cv;
    carea[t] = (cv.z - cv.x) * (cv.w - cv.y);
    __syncthreads();

    int rg = rb * CHUNK + t;
    if (rg >= N) return;
    float4 r = g_sboxes[rg];
    float ra = (r.z - r.x) * (r.w - r.y);

    u64 m0 = 0, m1 = 0;
    if (cb > rb) {
        #pragma unroll 32
        for (int j = 0; j < 64; j++) {
            float4 c = cbox[j];
            float ix1 = fmaxf(r.x, c.x), iy1 = fmaxf(r.y, c.y);
            float ix2 = fminf(r.z, c.z), iy2 = fminf(r.w, c.w);
            float inter = fmaxf(ix2 - ix1, 0.0f) * fmaxf(iy2 - iy1, 0.0f);
            if (3.0f * inter > ra + carea[j]) m0 |= 1ull << j;
        }
        #pragma unroll 32
        for (int j = 64; j < 128; j++) {
            float4 c = cbox[j];
            float ix1 = fmaxf(r.x, c.x), iy1 = fmaxf(r.y, c.y);
            float ix2 = fminf(r.z, c.z), iy2 = fminf(r.w, c.w);
            float inter = fmaxf(ix2 - ix1, 0.0f) * fmaxf(iy2 - iy1, 0.0f);
            if (3.0f * inter > ra + carea[j]) m1 |= 1ull << (j - 64);
        }
    } else {
        #pragma unroll 32
        for (int j = 0; j < 128; j++) {
            if (j <= t) continue;  // diagonal: only suppress later boxes
            float4 c = cbox[j];
            float ix1 = fmaxf(r.x, c.x), iy1 = fmaxf(r.y, c.y);
            float ix2 = fminf(r.z, c.z), iy2 = fminf(r.w, c.w);
            float inter = fmaxf(ix2 - ix1, 0.0f) * fmaxf(iy2 - iy1, 0.0f);
            if (3.0f * inter > ra + carea[j]) {
                if (j < 64) m0 |= 1ull << j; else m1 |= 1ull << (j - 64);
            }
        }
        g_diag[rg] = make_ulonglong2(m0, m1);
    }
    g_maskT[(size_t)cb * MAXN + rg] = make_ulonglong2(m0, m1);
}

__device__ __forceinline__ u64 vmask64(int valid) {
    return (valid >= 64) ? ~0ull : ((valid <= 0) ? 0ull : ((1ull << valid) - 1ull));
}

// ---------------------------------------------------------------------------
// phase A, optimistic batch version (R12, measured best).
// ---------------------------------------------------------------------------
__device__ __forceinline__ int phaseA_opt(const ulonglong2* d, u64 r0, u64 r1,
                                          int valid, int gbase, int* klist,
                                          u64& k0o, u64& k1o) {
    u64 P0 = ~r0 & vmask64(valid);
    u64 P1 = ~r1 & vmask64(valid - 64);
    u64 c0 = 0ull, c1 = 0ull;          // confirmed kept
    u64 sup0 = 0ull, sup1 = 0ull;      // suppression by confirmed kept
    int n = 0;
    while (P0 | P1) {
        int nck = n;                   // klist checkpoint
        u64 o0 = 0ull, o1 = 0ull;
        u64 t = P0;
        while (t) {
            int i = __ffsll((long long)t) - 1; t &= t - 1ull;
            klist[n++] = gbase + i;
            ulonglong2 dd = d[i];
            o0 |= dd.x; o1 |= dd.y;
        }
        t = P1;
        while (t) {
            int i = __ffsll((long long)t) - 1; t &= t - 1ull;
            klist[n++] = gbase + 64 + i;
            ulonglong2 dd = d[64 + i];
            o0 |= dd.x; o1 |= dd.y;
        }
        u64 x0 = (sup0 | o0) & P0, x1 = (sup1 | o1) & P1;
        if (!(x0 | x1)) { c0 |= P0; c1 |= P1; break; }   // happy path

        // conflict: first conflicted bit f
        n = nck;                       // rewind klist
        int f = x0 ? (__ffsll((long long)x0) - 1)
                   : (64 + __ffsll((long long)x1) - 1);
        u64 m0, m1;                    // bits strictly below f
        if (f < 64) { m0 = (1ull << f) - 1ull; m1 = 0ull; }
        else        { m0 = ~0ull;             m1 = (1ull << (f - 64)) - 1ull; }
        u64 nc0 = P0 & m0, nc1 = P1 & m1;     // newly confirmed
        c0 |= nc0; c1 |= nc1;
        t = nc0;
        while (t) {
            int i = __ffsll((long long)t) - 1; t &= t - 1ull;
            klist[n++] = gbase + i;
            ulonglong2 dd = d[i];
            sup0 |= dd.x; sup1 |= dd.y;
        }
        t = nc1;
        while (t) {
            int i = __ffsll((long long)t) - 1; t &= t - 1ull;
            klist[n++] = gbase + 64 + i;
            ulonglong2 dd = d[64 + i];
            sup0 |= dd.x; sup1 |= dd.y;
        }
        P0 = P0 & ~m0 & ~sup0;
        P1 = P1 & ~m1 & ~sup1;
        if (f < 64) P0 &= ~(1ull << f); else P1 &= ~(1ull << (f - 64));
    }
    k0o = c0; k1o = c1;
    return n;
}

// ---------------------------------------------------------------------------
// K3: lazy greedy scan, TWO chunks per round (39 rounds), optimistic phase A.
// Round (wc, wc+1):
//   threads 0-127:   gather word wc over klist[0..K)      -> s_part[0..3]
//   threads 128-255: gather word wc+1 over klist[0..K)    -> s_part[4..7]
//                    + stage maskT[wc+1][rows of chunk wc] -> s_stage
//                    + prefetch diag tiles wc+2, wc+3
//   ONE barrier; thread 0: reduce -> phaseA(wc) -> delta-patch word wc+1
//   with staged rows of wc's new kept (SMEM) -> phaseA(wc+1).
// Early termination once total kept >= MAXP.
// ---------------------------------------------------------------------------
__global__ void k_scan(int N, int W) {
    __shared__ ulonglong2 diagbuf[4][CHUNK];   // tiles wc..wc+3, slot = chunk&3
    __shared__ ulonglong2 s_stage[CHUNK];
    __shared__ ulonglong2 s_part[8];
    __shared__ int s_klist[KCAP];
    __shared__ int s_K, s_stop, s_cstop, s_total;
    int tid = threadIdx.x, lane = tid & 31, wid = tid >> 5;
    ulonglong2 Z = make_ulonglong2(0ull, 0ull);

    // prologue: load diag tiles 0..3
    for (int e = tid; e < 4 * CHUNK; e += 256) {
        int c = e >> 7, t = e & 127;
        int g = c * CHUNK + t;
        diagbuf[c][t] = (c < W && g < N) ? g_diag[g] : Z;
    }
    if (tid == 0) { s_stop = 0; s_cstop = W; s_total = 0; s_K = 0; }
    __syncthreads();

    // chunk 0
    if (tid == 0) {
        u64 k0, k1;
        int n = phaseA_opt(diagbuf[0], 0ull, 0ull, min(N, CHUNK), 0,
                           s_klist, k0, k1);
        g_keep[0] = make_ulonglong2(k0, k1);
        g_prefix[0] = 0;
        int tot = __popcll(k0) + __popcll(k1);
        s_total = tot; s_K = n;
        if (tot >= MAXP) { s_stop = 1; s_cstop = 1; }
    }
    __syncthreads();

    for (int wc = 1; wc < W; wc += 2) {
        if (s_stop) break;
        int K = s_K;
        bool has2 = (wc + 1 < W);

        // ---- phase 1 (one barrier per round) ----
        if (tid < 128) {
            // gather word wc
            const ulonglong2* mp = g_maskT + (size_t)wc * MAXN;
            u64 ax = 0ull, ay = 0ull;
            for (int t = tid; t < K; t += 128) {
                ulonglong2 v = mp[s_klist[t]];
                ax |= v.x; ay |= v.y;
            }
            #pragma unroll
            for (int o = 16; o; o >>= 1) {
                ax |= __shfl_xor_sync(~0u, ax, o);
                ay |= __shfl_xor_sync(~0u, ay, o);
            }
            if (lane == 0) s_part[wid] = make_ulonglong2(ax, ay);
        } else {
            int t = tid - 128;   // 0..127
            if (has2) {
                // gather word wc+1 over same klist snapshot
                const ulonglong2* mp = g_maskT + (size_t)(wc + 1) * MAXN;
                u64 ax = 0ull, ay = 0ull;
                for (int u = t; u < K; u += 128) {
                    ulonglong2 v = mp[s_klist[u]];
                    ax |= v.x; ay |= v.y;
                }
                #pragma unroll
                for (int o = 16; o; o >>= 1) {
                    ax |= __shfl_xor_sync(~0u, ax, o);
                    ay |= __shfl_xor_sync(~0u, ay, o);
                }
                if (lane == 0) s_part[wid] = make_ulonglong2(ax, ay);
                // stage maskT[wc+1][rows of chunk wc]
                s_stage[t] = mp[wc * CHUNK + t];
            }
            // prefetch diag tiles wc+2, wc+3
            if (wc + 2 < W) {
                int g = (wc + 2) * CHUNK + t;
                diagbuf[(wc + 2) & 3][t] = (g < N) ? g_diag[g] : Z;
            }
            if (wc + 3 < W) {
                int g = (wc + 3) * CHUNK + t;
                diagbuf[(wc + 3) & 3][t] = (g < N) ? g_diag[g] : Z;
            }
        }
        __syncthreads();

        // ---- phase 2: serial resolve of both chunks ----
        if (tid == 0) {
            // chunk wc
            u64 r0 = 0ull, r1 = 0ull;
            #pragma unroll
            for (int p = 0; p < 4; p++) {
                ulonglong2 v = s_part[p];
                r0 |= v.x; r1 |= v.y;
            }
            u64 k0, k1;
            int n1 = phaseA_opt(diagbuf[wc & 3], r0, r1, N - wc * CHUNK,
                                wc * CHUNK, s_klist + K, k0, k1);
            g_keep[wc] = make_ulonglong2(k0, k1);
            g_prefix[wc] = s_total;
            int tot = s_total + __popcll(k0) + __popcll(k1);
            int K2 = K + n1;
            if (tot >= MAXP) {
                s_total = tot; s_K = K2; s_stop = 1; s_cstop = wc + 1;
            } else if (has2) {
                // chunk wc+1: old gather + delta from staged rows of wc's kept
                u64 q0 = 0ull, q1 = 0ull;
                #pragma unroll
                for (int p = 4; p < 8; p++) {
                    ulonglong2 v = s_part[p];
                    q0 |= v.x; q1 |= v.y;
                }
                for (int t = K; t < K2; t++) {
                    ulonglong2 v = s_stage[s_klist[t] - wc * CHUNK];
                    q0 |= v.x; q1 |= v.y;
                }
                u64 j0, j1;
                int n2 = phaseA_opt(diagbuf[(wc + 1) & 3], q0, q1,
                                    N - (wc + 1) * CHUNK, (wc + 1) * CHUNK,
                                    s_klist + K2, j0, j1);
                g_keep[wc + 1] = make_ulonglong2(j0, j1);
                g_prefix[wc + 1] = tot;
                tot += __popcll(j0) + __popcll(j1);
                s_total = tot; s_K = K2 + n2;
                if (tot >= MAXP) { s_stop = 1; s_cstop = wc + 2; }
            } else {
                s_total = tot; s_K = K2;
            }
        }
        __syncthreads();
    }

    // chunks after the stop point can never contribute kept outputs
    int cstop = s_cstop;
    for (int c2 = cstop + tid; c2 < W; c2 += 256)
        g_keep[c2] = make_ulonglong2(0ull, 0ull);
}

// ---------------------------------------------------------------------------
// K4: apply MAX_PROPOSALS cutoff and emit outputs:
//   out[0 : 4N) boxes | out[4N : 5N) scores | out[5N : 6N) keep as 0/1
// ---------------------------------------------------------------------------
__global__ void k_out(float* __restrict__ out, int N) {
    int p = blockIdx.x * blockDim.x + threadIdx.x;
    if (p >= N) return;
    int c = p >> 7, i = p & 127;
    ulonglong2 kw = g_keep[c];
    bool kept;
    int below;
    if (i < 64) {
        kept  = (kw.x >> i) & 1ull;
        below = __popcll(kw.x & ((1ull << i) - 1ull));
    } else {
        int ii = i - 64;
        kept  = (kw.y >> ii) & 1ull;
        below = __popcll(kw.x) + __popcll(kw.y & ((1ull << ii) - 1ull));
    }
    int r = g_prefix[c] + below;
    bool fin = kept && (r < MAXP);

    float4 b = fin ? g_sboxes[p] : make_float4(0.f, 0.f, 0.f, 0.f);
    ((float4*)out)[p] = b;
    out[4 * N + p] = fin ? g_sscores[p] : 0.0f;
    out[5 * N + p] = fin ? 1.0f : 0.0f;
}

// ---------------------------------------------------------------------------
extern "C" void kernel_launch(void* const* d_in, const int* in_sizes, int n_in,
                              void* d_out, int out_size) {
    const float4* boxes  = (const float4*)d_in[0];
    const float*  scores = (const float*)d_in[1];
    int N = in_sizes[1];
    int W = (N + CHUNK - 1) / CHUNK;

    k_sortA<<<1, 1024>>>(scores, N);
    k_place<<<(N + 255) / 256, 256>>>(boxes, scores, N);

    dim3 g2(W, W);
    k_mask<<<g2, CHUNK>>>(N, W);

    k_scan<<<1, 256>>>(N, W);

    k_out<<<(N + 255) / 256, 256>>>((float*)d_out, N);
}

// round 16
// speedup vs baseline: 1.3005x; 1.0571x over previous
#include <cuda_runtime.h>

#define CHUNK  128
#define MAXW   79
#define MAXN   (MAXW * CHUNK)   // 10112
#define MAXP   1000
#define SB     4096

typedef unsigned long long u64;

// ---- static device scratch (no allocations allowed) ----
__device__ ulonglong2 g_maskT[(size_t)MAXW * MAXN];  // [word][row] suppression bits
__device__ ulonglong2 g_diag[MAXN];                  // diagonal-block masks
__device__ float4     g_sboxes[MAXN];                // boxes in sorted order
__device__ float      g_sscores[MAXN];               // scores in sorted order
__device__ u64        g_keepx[MAXW], g_keepy[MAXW];  // keep bits per chunk
__device__ int        g_prefix[MAXW];                // rank base per chunk
__device__ int        g_total[MAXW];                 // cumulative kept through c
__device__ volatile int g_flag[MAXW];                // publish flags (chain)
__device__ volatile int g_stopat;                    // first chunk past MAXP
__device__ int        g_base[SB];                    // bucket base (descending)
__device__ int        g_members[MAXN];               // indices grouped by bucket

__device__ __forceinline__ int bucket_of(float s) {
    int b = (int)(s * 4096.0f);           // monotone for s >= 0
    return max(0, min(SB - 1, b));
}

// ---------------------------------------------------------------------------
// S1: fused single-block sort front-end + chain-state reset for this replay.
// ---------------------------------------------------------------------------
__global__ void k_sortA(const float* __restrict__ scores, int N) {
    __shared__ int s_cnt[SB];
    __shared__ int s_base[SB];
    __shared__ int wsum[32];
    int tid = threadIdx.x, lane = tid & 31, wid = tid >> 5;

    // reset chain state (k_chain runs later in the same stream)
    if (tid < MAXW) g_flag[tid] = 0;
    if (tid == 0) g_stopat = 0x7fffffff;

    for (int b = tid; b < SB; b += 1024) s_cnt[b] = 0;
    __syncthreads();
    for (int i = tid; i < N; i += 1024)
        atomicAdd(&s_cnt[bucket_of(scores[i])], 1);
    __syncthreads();

    int cbase = 0;
    for (int k = 0; k < SB / 1024; k++) {
        int b = SB - 1 - (k * 1024 + tid);   // descending bucket order
        int v = s_cnt[b];
        int x = v;
        #pragma unroll
        for (int o = 1; o < 32; o <<= 1) {
            int y = __shfl_up_sync(~0u, x, o);
            if (lane >= o) x += y;
        }
        if (lane == 31) wsum[wid] = x;
        __syncthreads();
        if (wid == 0) {
            int s = wsum[lane];
            #pragma unroll
            for (int o = 1; o < 32; o <<= 1) {
                int y = __shfl_up_sync(~0u, s, o);
                if (lane >= o) s += y;
            }
            wsum[lane] = s;
        }
        __syncthreads();
        s_base[b] = cbase + (x - v) + (wid ? wsum[wid - 1] : 0);
        cbase += wsum[31];
        __syncthreads();
    }

    for (int b = tid; b < SB; b += 1024) { s_cnt[b] = 0; g_base[b] = s_base[b]; }
    __syncthreads();
    for (int i = tid; i < N; i += 1024) {
        int b = bucket_of(scores[i]);
        int slot = s_base[b] + atomicAdd(&s_cnt[b], 1);
        g_members[slot] = i;
    }
}

// ---------------------------------------------------------------------------
// S2: exact stable rank within bucket + scatter (grid-parallel).
// ---------------------------------------------------------------------------
__global__ void k_place(const float4* __restrict__ boxes,
                        const float* __restrict__ scores, int N) {
    int i = blockIdx.x * blockDim.x + threadIdx.x;
    if (i >= N) return;
    float si = scores[i];
    int b = bucket_of(si);
    int base = g_base[b];
    int cb   = ((b > 0) ? g_base[b - 1] : N) - base;
    int r = base;
    for (int t = 0; t < cb; t++) {
        int j = g_members[base + t];
        if (j == i) continue;
        float sj = scores[j];
        r += (sj > si) || (sj == si && j < i);
    }
    g_sboxes[r]  = boxes[i];
    g_sscores[r] = si;
}

// ---------------------------------------------------------------------------
// K2: pairwise IoU suppression bitmask, 128x128 tiles, upper triangle.
// suppress <=> IoU > 0.5 <=> 3*inter > areaR + areaC  (division-free).
// Stores TRANSPOSED: g_maskT[word][row].
// ---------------------------------------------------------------------------
__global__ void k_mask(int N, int W) {
    int cb = blockIdx.x, rb = blockIdx.y;
    if (cb < rb) return;
    __shared__ float4 cbox[CHUNK];
    __shared__ float  carea[CHUNK];
    int t  = threadIdx.x;
    int cg = cb * CHUNK + t;
    float4 cv = (cg < N) ? g_sboxes[cg] : make_float4(0.f, 0.f, 0.f, 0.f);
    cbox[t]  = cv;
    carea[t] = (cv.z - cv.x) * (cv.w - cv.y);
    __syncthreads();

    int rg = rb * CHUNK + t;
    if (rg >= N) return;
    float4 r = g_sboxes[rg];
    float ra = (r.z - r.x) * (r.w - r.y);

    u64 m0 = 0, m1 = 0;
    if (cb > rb) {
        #pragma unroll 32
        for (int j = 0; j < 64; j++) {
            float4 c = cbox[j];
            float ix1 = fmaxf(r.x, c.x), iy1 = fmaxf(r.y, c.y);
            float ix2 = fminf(r.z, c.z), iy2 = fminf(r.w, c.w);
            float inter = fmaxf(ix2 - ix1, 0.0f) * fmaxf(iy2 - iy1, 0.0f);
            if (3.0f * inter > ra + carea[j]) m0 |= 1ull << j;
        }
        #pragma unroll 32
        for (int j = 64; j < 128; j++) {
            float4 c = cbox[j];
            float ix1 = fmaxf(r.x, c.x), iy1 = fmaxf(r.y, c.y);
            float ix2 = fminf(r.z, c.z), iy2 = fminf(r.w, c.w);
            float inter = fmaxf(ix2 - ix1, 0.0f) * fmaxf(iy2 - iy1, 0.0f);
            if (3.0f * inter > ra + carea[j]) m1 |= 1ull << (j - 64);
        }
    } else {
        #pragma unroll 32
        for (int j = 0; j < 128; j++) {
            if (j <= t) continue;  // diagonal: only suppress later boxes
            float4 c = cbox[j];
            float ix1 = fmaxf(r.x, c.x), iy1 = fmaxf(r.y, c.y);
            float ix2 = fminf(r.z, c.z), iy2 = fminf(r.w, c.w);
            float inter = fmaxf(ix2 - ix1, 0.0f) * fmaxf(iy2 - iy1, 0.0f);
            if (3.0f * inter > ra + carea[j]) {
                if (j < 64) m0 |= 1ull << j; else m1 |= 1ull << (j - 64);
            }
        }
        g_diag[rg] = make_ulonglong2(m0, m1);
    }
    g_maskT[(size_t)cb * MAXN + rg] = make_ulonglong2(m0, m1);
}

__device__ __forceinline__ u64 vmask64(int valid) {
    return (valid >= 64) ? ~0ull : ((valid <= 0) ? 0ull : ((1ull << valid) - 1ull));
}

// ---------------------------------------------------------------------------
// phase A, optimistic batch version (no klist; counts via popcount).
// ---------------------------------------------------------------------------
__device__ __forceinline__ int phaseA_nk(const ulonglong2* d, u64 r0, u64 r1,
                                         int valid, u64& k0o, u64& k1o) {
    u64 P0 = ~r0 & vmask64(valid);
    u64 P1 = ~r1 & vmask64(valid - 64);
    u64 c0 = 0ull, c1 = 0ull, sup0 = 0ull, sup1 = 0ull;
    while (P0 | P1) {
        u64 o0 = 0ull, o1 = 0ull;
        u64 t = P0;
        while (t) {
            int i = __ffsll((long long)t) - 1; t &= t - 1ull;
            ulonglong2 dd = d[i];
            o0 |= dd.x; o1 |= dd.y;
        }
        t = P1;
        while (t) {
            int i = __ffsll((long long)t) - 1; t &= t - 1ull;
            ulonglong2 dd = d[64 + i];
            o0 |= dd.x; o1 |= dd.y;
        }
        u64 x0 = (sup0 | o0) & P0, x1 = (sup1 | o1) & P1;
        if (!(x0 | x1)) { c0 |= P0; c1 |= P1; break; }   // happy path

        int f = x0 ? (__ffsll((long long)x0) - 1)
                   : (64 + __ffsll((long long)x1) - 1);
        u64 m0, m1;                    // bits strictly below f
        if (f < 64) { m0 = (1ull << f) - 1ull; m1 = 0ull; }
        else        { m0 = ~0ull;             m1 = (1ull << (f - 64)) - 1ull; }
        u64 nc0 = P0 & m0, nc1 = P1 & m1;     // newly confirmed kept
        c0 |= nc0; c1 |= nc1;
        t = nc0;
        while (t) {
            int i = __ffsll((long long)t) - 1; t &= t - 1ull;
            ulonglong2 dd = d[i];
            sup0 |= dd.x; sup1 |= dd.y;
        }
        t = nc1;
        while (t) {
            int i = __ffsll((long long)t) - 1; t &= t - 1ull;
            ulonglong2 dd = d[64 + i];
            sup0 |= dd.x; sup1 |= dd.y;
        }
        P0 = P0 & ~m0 & ~sup0;
        P1 = P1 & ~m1 & ~sup1;
        if (f < 64) P0 &= ~(1ull << f); else P1 &= ~(1ull << (f - 64));
    }
    k0o = c0; k1o = c1;
    return __popcll(c0) + __popcll(c1);
}

// ---------------------------------------------------------------------------
// K3: cross-block wavefront scan. Block c owns chunk c (all W blocks
// co-resident: W=79 < 148 SMs). Block c:
//   - prestages diag tile + maskT[c][rows of chunk c-1] into smem;
//   - for d=0..c-1: poll flag[d]; 128-thread predicated gather of kept rows
//     (smem tile for d=c-1, L2 for earlier) + shfl-OR reduce into acc;
//   - thread 0: optimistic phase A; publish keep/prefix/total + flag.
// Early MAXP exit broadcast via g_stopat.
// ---------------------------------------------------------------------------
__global__ void __launch_bounds__(CHUNK, 1) k_chain(int N, int W) {
    __shared__ ulonglong2 sdiag[CHUNK];
    __shared__ ulonglong2 stile[CHUNK];
    __shared__ ulonglong2 s_red[4];
    __shared__ u64 s_kx, s_ky;
    __shared__ int s_exit;
    int c = blockIdx.x, t = threadIdx.x;
    int lane = t & 31, wid = t >> 5;
    ulonglong2 Z = make_ulonglong2(0ull, 0ull);

    int g = c * CHUNK + t;
    sdiag[t] = (g < N) ? g_diag[g] : Z;
    if (c > 0)
        stile[t] = g_maskT[(size_t)c * MAXN + (c - 1) * CHUNK + t];
    __syncthreads();

    u64 acc0 = 0ull, acc1 = 0ull;   // thread 0 only
    int prev_total = 0;             // thread 0 only

    for (int d = 0; d < c; d++) {
        if (t == 0) {
            int e = 0;
            while (g_flag[d] == 0) {
                if (g_stopat <= c) { e = 1; break; }
            }
            if (!e) {
                s_kx = ((volatile u64*)g_keepx)[d];
                s_ky = ((volatile u64*)g_keepy)[d];
                prev_total = ((volatile int*)g_total)[d];
                if (prev_total >= MAXP) {
                    atomicMin((int*)&g_stopat, c);
                    e = 1;
                }
            }
            s_exit = e;
        }
        __syncthreads();
        if (s_exit) {
            if (t == 0) {
                ((volatile u64*)g_keepx)[c] = 0ull;
                ((volatile u64*)g_keepy)[c] = 0ull;
                g_prefix[c] = 0;
                ((volatile int*)g_total)[c] = MAXP;   // >= MAXP: stop marker
                __threadfence();
                g_flag[c] = 1;
            }
            return;
        }

        // predicated gather of chunk d's kept rows + block OR-reduce
        u64 kx = s_kx, ky = s_ky;
        bool kb = (t < 64) ? ((kx >> t) & 1ull) : ((ky >> (t - 64)) & 1ull);
        u64 vx = 0ull, vy = 0ull;
        if (kb) {
            ulonglong2 v = (d == c - 1)
                ? stile[t]
                : g_maskT[(size_t)c * MAXN + d * CHUNK + t];
            vx = v.x; vy = v.y;
        }
        #pragma unroll
        for (int o = 16; o; o >>= 1) {
            vx |= __shfl_xor_sync(~0u, vx, o);
            vy |= __shfl_xor_sync(~0u, vy, o);
        }
        if (lane == 0) s_red[wid] = make_ulonglong2(vx, vy);
        __syncthreads();
        if (t == 0) {
            #pragma unroll
            for (int w = 0; w < 4; w++) {
                ulonglong2 v = s_red[w];
                acc0 |= v.x; acc1 |= v.y;
            }
        }
        __syncthreads();
    }

    // resolve own chunk + publish
    if (t == 0) {
        u64 k0, k1;
        int n = phaseA_nk(sdiag, acc0, acc1, N - c * CHUNK, k0, k1);
        ((volatile u64*)g_keepx)[c] = k0;
        ((volatile u64*)g_keepy)[c] = k1;
        g_prefix[c] = prev_total;
        ((volatile int*)g_total)[c] = prev_total + n;
        __threadfence();
        g_flag[c] = 1;
    }
}

// ---------------------------------------------------------------------------
// K4: apply MAX_PROPOSALS cutoff and emit outputs:
//   out[0 : 4N) boxes | out[4N : 5N) scores | out[5N : 6N) keep as 0/1
// ---------------------------------------------------------------------------
__global__ void k_out(float* __restrict__ out, int N) {
    int p = blockIdx.x * blockDim.x + threadIdx.x;
    if (p >= N) return;
    int c = p >> 7, i = p & 127;
    u64 kx = g_keepx[c], ky = g_keepy[c];
    bool kept;
    int below;
    if (i < 64) {
        kept  = (kx >> i) & 1ull;
        below = __popcll(kx & ((1ull << i) - 1ull));
    } else {
        int ii = i - 64;
        kept  = (ky >> ii) & 1ull;
        below = __popcll(kx) + __popcll(ky & ((1ull << ii) - 1ull));
    }
    int r = g_prefix[c] + below;
    bool fin = kept && (r < MAXP);

    float4 b = fin ? g_sboxes[p] : make_float4(0.f, 0.f, 0.f, 0.f);
    ((float4*)out)[p] = b;
    out[4 * N + p] = fin ? g_sscores[p] : 0.0f;
    out[5 * N + p] = fin ? 1.0f : 0.0f;
}

// ---------------------------------------------------------------------------
extern "C" void kernel_launch(void* const* d_in, const int* in_sizes, int n_in,
                              void* d_out, int out_size) {
    const float4* boxes  = (const float4*)d_in[0];
    const float*  scores = (const float*)d_in[1];
    int N = in_sizes[1];
    int W = (N + CHUNK - 1) / CHUNK;

    k_sortA<<<1, 1024>>>(scores, N);
    k_place<<<(N + 255) / 256, 256>>>(boxes, scores, N);

    dim3 g2(W, W);
    k_mask<<<g2, CHUNK>>>(N, W);

    k_chain<<<W, CHUNK>>>(N, W);

    k_out<<<(N + 255) / 256, 256>>>((float*)d_out, N);
}